// round 4
// baseline (speedup 1.0000x reference)
#include <cuda_runtime.h>

#define B_SZ   64
#define FEAT   512
#define NB     8
#define H_SZ   1024
#define WR     513            // W/2 + 1
#define HWR    (H_SZ * WR)    // 525312, divisible by 4
#define NQUAD  (HWR / 4)      // 131328
#define TPB    128
#define GRIDX  (NQUAD / TPB)  // 1026 exactly
#define BGRP   4              // plane groups (blockIdx.y)
#define PPG    (B_SZ / BGRP)  // 16 planes per group
#define NBLK   (GRIDX * BGRP) // 4104

// Inter-block handshake state (persists across graph replays; reset in-kernel).
__device__ float g_bw[B_SZ * NB];
__device__ int   g_ready;     // zero-initialized; producers count to 64
__device__ int   g_done;      // zero-initialized; blocks count to NBLK

// ---------------------------------------------------------------------------
// Fused kernel, b-loop split over blockIdx.y for 4x occupancy.
//  Producers: blocks (x<16, y==0) -> linear bids 0..15, wave-1 resident.
//    warp w = batch row b: 8 dots (feat reuse across bands), softmax,
//    publish g_bw[b], bump g_ready.
//  All blocks: 4 band indices (weight-independent), spin on g_ready,
//    load their 16x9 LUT slice (slot 8 = 0 handles r==max_r), then stream
//    16 float4 __stcs stores per thread.
//  Last block resets g_ready/g_done for the next graph replay.
// ---------------------------------------------------------------------------
__global__ void __launch_bounds__(TPB) fused_freqmask_kernel(
        const float* __restrict__ feat,
        const float* __restrict__ wmat,
        const float* __restrict__ bias,
        float* __restrict__ out) {

    const int lane = threadIdx.x & 31;
    const int warp = threadIdx.x >> 5;

    // ---------------- producer: 16 blocks, one warp per batch row ----------
    if (blockIdx.y == 0 && blockIdx.x < 16) {
        const int b = blockIdx.x * 4 + warp;      // 0..63
        const float* f = feat + b * FEAT;

        float acc[NB];
        #pragma unroll
        for (int i = 0; i < NB; i++) acc[i] = 0.0f;

        #pragma unroll
        for (int k = lane; k < FEAT; k += 32) {
            float fv = f[k];
            #pragma unroll
            for (int i = 0; i < NB; i++)
                acc[i] += fv * wmat[i * FEAT + k];
        }
        #pragma unroll
        for (int i = 0; i < NB; i++)
            #pragma unroll
            for (int o = 16; o; o >>= 1)
                acc[i] += __shfl_down_sync(0xffffffffu, acc[i], o);

        if (lane == 0) {
            float lg[NB];
            float m = -1e30f;
            #pragma unroll
            for (int i = 0; i < NB; i++) {
                lg[i] = acc[i] + bias[i];
                m = fmaxf(m, lg[i]);
            }
            float s = 0.0f;
            #pragma unroll
            for (int i = 0; i < NB; i++) {
                lg[i] = expf(lg[i] - m);
                s += lg[i];
            }
            float inv = 1.0f / s;
            #pragma unroll
            for (int i = 0; i < NB; i++)
                g_bw[b * NB + i] = lg[i] * inv;
            __threadfence();
            atomicAdd(&g_ready, 1);
        }
    }

    // ---------------- band indices (independent of weights) ----------------
    const int base = (blockIdx.x * TPB + threadIdx.x) * 4;   // always < HWR
    const float max_r = sqrtf(0.5f);                          // bit-exact

    int band[4];
    #pragma unroll
    for (int j = 0; j < 4; j++) {
        int p  = base + j;
        int h  = p / WR;
        int wc = p - h * WR;
        float u = (float)wc * (1.0f / 1024.0f);
        float v = (float)(h < H_SZ / 2 ? h : h - H_SZ) * (1.0f / 1024.0f);
        float r = sqrtf(u * u + v * v);                       // exact args

        int bi = 0;
        #pragma unroll
        for (int i = 1; i < NB; i++)
            bi += (r >= max_r * ((float)i / (float)NB)) ? 1 : 0;
        band[j] = (r >= max_r) ? 8 : bi;                      // 8 -> zero slot
    }

    // ---------------- wait for all 64 producer rows ------------------------
    if (threadIdx.x == 0) {
        while (*(volatile int*)&g_ready != B_SZ)
            __nanosleep(64);
    }
    __syncthreads();
    __threadfence();   // acquire: order LUT loads after flag observation

    // LUT slice for this block's 16 planes
    const int b0 = blockIdx.y * PPG;
    __shared__ float bw[PPG * 9];
    for (int i = threadIdx.x; i < PPG * 9; i += TPB) {
        int b = i / 9, s = i - b * 9;
        bw[i] = (s < NB) ? g_bw[(b0 + b) * NB + s] : 0.0f;
    }
    __syncthreads();

    // ---------------- streaming stores: 16 planes x float4 -----------------
    float* o = out + (size_t)b0 * HWR + base;
    #pragma unroll
    for (int b = 0; b < PPG; b++) {
        const float* row = bw + b * 9;
        float4 v4;
        v4.x = row[band[0]];
        v4.y = row[band[1]];
        v4.z = row[band[2]];
        v4.w = row[band[3]];
        __stcs(reinterpret_cast<float4*>(o + (size_t)b * HWR), v4);
    }

    // ---------------- reset handshake state for next graph replay ----------
    __syncthreads();
    if (threadIdx.x == 0) {
        int d = atomicAdd(&g_done, 1);
        if (d == NBLK - 1) {
            g_ready = 0;
            g_done  = 0;
            __threadfence();
        }
    }
}

// ---------------------------------------------------------------------------
extern "C" void kernel_launch(void* const* d_in, const int* in_sizes, int n_in,
                              void* d_out, int out_size) {
    const float* feat = (const float*)d_in[0];  // [64, 512]
    const float* w    = (const float*)d_in[1];  // [8, 512]
    const float* bias = (const float*)d_in[2];  // [8]
    float* out = (float*)d_out;                 // [64, 1, 1024, 513] fp32

    dim3 grid(GRIDX, BGRP);
    fused_freqmask_kernel<<<grid, TPB>>>(feat, w, bias, out);
}

// round 5
// speedup vs baseline: 1.1921x; 1.1921x over previous
#include <cuda_runtime.h>

#define B_SZ   64
#define FEAT   512
#define NB     8
#define H_SZ   1024
#define WR     513            // W/2 + 1
#define HWR    (H_SZ * WR)    // 525312, divisible by 4
#define NQUAD  (HWR / 4)      // 131328
#define TPB    128
#define GRIDX  (NQUAD / TPB)  // 1026 exactly -> 6.93 blocks/SM, 1% imbalance

// Scratch for band weights between kernels (no cudaMalloc allowed).
__device__ float g_bw[B_SZ * NB];

// ---------------------------------------------------------------------------
// Kernel 1: logits = feat @ w.T + bias ; softmax over 8 bands.
// grid = 16 blocks x 128 thr; warp = one batch row; feat value loaded once
// per lane and reused across all 8 bands.
// ---------------------------------------------------------------------------
__global__ void __launch_bounds__(TPB) mlp_softmax_kernel(
        const float* __restrict__ feat,
        const float* __restrict__ wmat,
        const float* __restrict__ bias) {
    const int lane = threadIdx.x & 31;
    const int warp = threadIdx.x >> 5;
    const int b    = blockIdx.x * 4 + warp;       // 0..63

    const float* f = feat + b * FEAT;

    float acc[NB];
    #pragma unroll
    for (int i = 0; i < NB; i++) acc[i] = 0.0f;

    #pragma unroll
    for (int k = lane; k < FEAT; k += 32) {
        float fv = f[k];
        #pragma unroll
        for (int i = 0; i < NB; i++)
            acc[i] += fv * wmat[i * FEAT + k];
    }
    #pragma unroll
    for (int i = 0; i < NB; i++)
        #pragma unroll
        for (int o = 16; o; o >>= 1)
            acc[i] += __shfl_down_sync(0xffffffffu, acc[i], o);

    if (lane == 0) {
        float lg[NB];
        float m = -1e30f;
        #pragma unroll
        for (int i = 0; i < NB; i++) {
            lg[i] = acc[i] + bias[i];
            m = fmaxf(m, lg[i]);
        }
        float s = 0.0f;
        #pragma unroll
        for (int i = 0; i < NB; i++) {
            lg[i] = expf(lg[i] - m);
            s += lg[i];
        }
        float inv = 1.0f / s;
        #pragma unroll
        for (int i = 0; i < NB; i++)
            g_bw[b * NB + i] = lg[i] * inv;
    }
}

// ---------------------------------------------------------------------------
// Kernel 2: fill the [64, 1024, 513] output.
// Thread = 4 consecutive pixels; band index computed once per pixel, reused
// across all 64 batch planes with a float4 store each. 128-thread blocks
// (1026 blocks, single wave, ~1% per-SM imbalance vs 15% at 256 thr).
// Shared LUT is [64][9]: slot 8 = 0.0f handles the r == max_r pixel.
// ---------------------------------------------------------------------------
__global__ void __launch_bounds__(TPB) fill_kernel(float* __restrict__ out) {
    __shared__ float bw[B_SZ * 9];
    for (int i = threadIdx.x; i < B_SZ * 9; i += TPB) {
        int b = i / 9, s = i - b * 9;
        bw[i] = (s < NB) ? g_bw[b * NB + s] : 0.0f;
    }

    const int base = (blockIdx.x * TPB + threadIdx.x) * 4;   // always < HWR
    const float max_r = sqrtf(0.5f);                          // bit-exact

    int band[4];
    #pragma unroll
    for (int j = 0; j < 4; j++) {
        int p  = base + j;
        int h  = p / WR;
        int wc = p - h * WR;
        float u = (float)wc * (1.0f / 1024.0f);                 // rfftfreq
        float v = (float)(h < H_SZ / 2 ? h : h - H_SZ) * (1.0f / 1024.0f);
        float r = sqrtf(u * u + v * v);                          // exact args

        int bi = 0;
        #pragma unroll
        for (int i = 1; i < NB; i++)
            bi += (r >= max_r * ((float)i / (float)NB)) ? 1 : 0;
        band[j] = (r >= max_r) ? 8 : bi;   // sentinel -> zero slot
    }

    __syncthreads();

    float* o = out + base;
    #pragma unroll 4
    for (int b = 0; b < B_SZ; b++) {
        const float* row = bw + b * 9;
        float4 v4;
        v4.x = row[band[0]];
        v4.y = row[band[1]];
        v4.z = row[band[2]];
        v4.w = row[band[3]];
        *reinterpret_cast<float4*>(o + (size_t)b * HWR) = v4;
    }
}

// ---------------------------------------------------------------------------
extern "C" void kernel_launch(void* const* d_in, const int* in_sizes, int n_in,
                              void* d_out, int out_size) {
    const float* feat = (const float*)d_in[0];  // [64, 512]
    const float* w    = (const float*)d_in[1];  // [8, 512]
    const float* bias = (const float*)d_in[2];  // [8]
    float* out = (float*)d_out;                 // [64, 1, 1024, 513] fp32

    mlp_softmax_kernel<<<16, TPB>>>(feat, w, bias);
    fill_kernel<<<GRIDX, TPB>>>(out);
}

// round 6
// speedup vs baseline: 1.2332x; 1.0345x over previous
#include <cuda_runtime.h>

#define B_SZ   64
#define FEAT   512
#define NB     8
#define H_SZ   1024
#define WR     513            // W/2 + 1
#define HWR    (H_SZ * WR)    // 525312, divisible by 4
#define NQUAD  (HWR / 4)      // 131328
#define TPB    128
#define GRIDX  (NQUAD / TPB)  // 1026 exactly

// Scratch for band weights between kernels (no cudaMalloc allowed).
__device__ float g_bw[B_SZ * NB];

// ---------------------------------------------------------------------------
// Kernel 1 (primary): logits = feat @ w.T + bias ; softmax over 8 bands.
// 64 blocks x 256 thr, warp = one (b, band) pair — the fastest measured
// config (R1). Fires launch_dependents immediately so the PDL-gated fill
// kernel starts while this one runs.
// ---------------------------------------------------------------------------
__global__ void __launch_bounds__(256) mlp_softmax_kernel(
        const float* __restrict__ feat,
        const float* __restrict__ wmat,
        const float* __restrict__ bias) {
    asm volatile("griddepcontrol.launch_dependents;");

    const int b    = blockIdx.x;
    const int warp = threadIdx.x >> 5;   // band
    const int lane = threadIdx.x & 31;

    const float* f  = feat + b * FEAT;
    const float* wr = wmat + warp * FEAT;

    float acc = 0.0f;
    #pragma unroll
    for (int k = lane; k < FEAT; k += 32)
        acc += f[k] * wr[k];

    #pragma unroll
    for (int o = 16; o; o >>= 1)
        acc += __shfl_down_sync(0xffffffffu, acc, o);

    __shared__ float sl[NB];
    __shared__ float se[NB];
    if (lane == 0) sl[warp] = acc + bias[warp];
    __syncthreads();

    if (threadIdx.x < NB) {
        float m = sl[0];
        #pragma unroll
        for (int i = 1; i < NB; i++) m = fmaxf(m, sl[i]);
        se[threadIdx.x] = expf(sl[threadIdx.x] - m);
    }
    __syncthreads();

    if (threadIdx.x < NB) {
        float s = 0.0f;
        #pragma unroll
        for (int i = 0; i < NB; i++) s += se[i];
        g_bw[b * NB + threadIdx.x] = se[threadIdx.x] / s;
    }
}

// ---------------------------------------------------------------------------
// Kernel 2 (PDL dependent): fill the [64, 1024, 513] output.
// Band indices (weight-independent) are computed BEFORE griddepcontrol.wait,
// overlapping the primary kernel. After the wait (which guarantees the
// primary's g_bw writes are visible), load the 64x9 LUT and stream stores.
// Slot 8 = 0.0f handles the single r == max_r pixel.
// ---------------------------------------------------------------------------
__global__ void __launch_bounds__(TPB) fill_kernel(float* __restrict__ out) {
    const int base = (blockIdx.x * TPB + threadIdx.x) * 4;   // always < HWR
    const float max_r = sqrtf(0.5f);                          // bit-exact

    int band[4];
    #pragma unroll
    for (int j = 0; j < 4; j++) {
        int p  = base + j;
        int h  = p / WR;
        int wc = p - h * WR;
        float u = (float)wc * (1.0f / 1024.0f);                 // rfftfreq
        float v = (float)(h < H_SZ / 2 ? h : h - H_SZ) * (1.0f / 1024.0f);
        float r = sqrtf(u * u + v * v);                          // exact args

        int bi = 0;
        #pragma unroll
        for (int i = 1; i < NB; i++)
            bi += (r >= max_r * ((float)i / (float)NB)) ? 1 : 0;
        band[j] = (r >= max_r) ? 8 : bi;   // sentinel -> zero slot
    }

    // Wait for the primary grid to complete (makes g_bw visible).
    asm volatile("griddepcontrol.wait;" ::: "memory");

    __shared__ float bw[B_SZ * 9];
    for (int i = threadIdx.x; i < B_SZ * 9; i += TPB) {
        int b = i / 9, s = i - b * 9;
        bw[i] = (s < NB) ? g_bw[b * NB + s] : 0.0f;
    }
    __syncthreads();

    float* o = out + base;
    #pragma unroll 4
    for (int b = 0; b < B_SZ; b++) {
        const float* row = bw + b * 9;
        float4 v4;
        v4.x = row[band[0]];
        v4.y = row[band[1]];
        v4.z = row[band[2]];
        v4.w = row[band[3]];
        *reinterpret_cast<float4*>(o + (size_t)b * HWR) = v4;
    }
}

// ---------------------------------------------------------------------------
extern "C" void kernel_launch(void* const* d_in, const int* in_sizes, int n_in,
                              void* d_out, int out_size) {
    const float* feat = (const float*)d_in[0];  // [64, 512]
    const float* w    = (const float*)d_in[1];  // [8, 512]
    const float* bias = (const float*)d_in[2];  // [8]
    float* out = (float*)d_out;                 // [64, 1, 1024, 513] fp32

    mlp_softmax_kernel<<<64, 256>>>(feat, w, bias);

    // Dependent launch with programmatic stream serialization (PDL).
    cudaLaunchConfig_t cfg = {};
    cfg.gridDim  = dim3(GRIDX, 1, 1);
    cfg.blockDim = dim3(TPB, 1, 1);
    cfg.dynamicSmemBytes = 0;
    cfg.stream = 0;
    cudaLaunchAttribute attrs[1];
    attrs[0].id = cudaLaunchAttributeProgrammaticStreamSerialization;
    attrs[0].val.programmaticStreamSerializationAllowed = 1;
    cfg.attrs = attrs;
    cfg.numAttrs = 1;
    cudaLaunchKernelEx(&cfg, fill_kernel, out);
}

// round 7
// speedup vs baseline: 1.4788x; 1.1991x over previous
#include <cuda_runtime.h>

#define B_SZ   64
#define FEAT   512
#define NB     8
#define H_SZ   1024
#define WR     513            // W/2 + 1
#define HWR    (H_SZ * WR)    // 525312, divisible by 4
#define NQUAD  (HWR / 4)      // 131328
#define TPB    128
#define GRID   (NQUAD / TPB)  // 1026 exactly, single wave, all co-resident

// Handshake state (persists across graph replays; reset in-kernel).
__device__ float g_bw[B_SZ * NB];
__device__ int   g_ready;     // zero-init; producers release-add to 64
__device__ int   g_done;      // zero-init; blocks count to GRID

__device__ __forceinline__ int ld_acquire_gpu(const int* p) {
    int v;
    asm volatile("ld.acquire.gpu.global.s32 %0, [%1];" : "=r"(v) : "l"(p) : "memory");
    return v;
}
__device__ __forceinline__ void red_release_add(int* p, int v) {
    asm volatile("red.release.gpu.global.add.s32 [%0], %1;" :: "l"(p), "r"(v) : "memory");
}

// ---------------------------------------------------------------------------
// Fused kernel.
//  Producers: blocks 0..63 (wave-1 resident), block b computes batch row b:
//    FEAT split across 4 warps (4 elems/lane), 8-band accumulators, smem
//    reduce, 8-thread softmax, release-publish g_bw[b].
//  All blocks: 4 band indices (weight-independent, overlaps producers), then
//    acquire-spin on g_ready==64, load 64x9 LUT (slot 8 = 0 for r==max_r),
//    stream 64 float4 __stcs stores per thread.
//  Last block resets handshake for the next graph replay.
// ---------------------------------------------------------------------------
__global__ void __launch_bounds__(TPB) fused_freqmask_kernel(
        const float* __restrict__ feat,
        const float* __restrict__ wmat,
        const float* __restrict__ bias,
        float* __restrict__ out) {

    const int lane = threadIdx.x & 31;
    const int warp = threadIdx.x >> 5;

    __shared__ float pacc[4][NB];   // per-warp partial dots
    __shared__ float se[NB];

    // ---------------- producer: blocks 0..63, one block per batch row ------
    if (blockIdx.x < B_SZ) {
        const int b = blockIdx.x;
        const float* f = feat + b * FEAT;

        float acc[NB];
        #pragma unroll
        for (int i = 0; i < NB; i++) acc[i] = 0.0f;

        // thread t covers k = t, t+128, t+256, t+384
        #pragma unroll
        for (int kk = 0; kk < FEAT / TPB; kk++) {
            int k = threadIdx.x + kk * TPB;
            float fv = f[k];
            #pragma unroll
            for (int i = 0; i < NB; i++)
                acc[i] += fv * wmat[i * FEAT + k];
        }
        #pragma unroll
        for (int i = 0; i < NB; i++)
            #pragma unroll
            for (int o = 16; o; o >>= 1)
                acc[i] += __shfl_down_sync(0xffffffffu, acc[i], o);
        if (lane == 0)
            #pragma unroll
            for (int i = 0; i < NB; i++) pacc[warp][i] = acc[i];
        __syncthreads();

        if (threadIdx.x < NB) {
            int i = threadIdx.x;
            float lg = pacc[0][i] + pacc[1][i] + pacc[2][i] + pacc[3][i] + bias[i];
            se[i] = lg;
        }
        __syncthreads();
        if (threadIdx.x < NB) {
            int i = threadIdx.x;
            float m = se[0];
            #pragma unroll
            for (int j = 1; j < NB; j++) m = fmaxf(m, se[j]);
            float e = expf(se[i] - m);
            // broadcast exps via shuffle within the first warp (threads 0..7)
            float s = 0.0f;
            #pragma unroll
            for (int j = 0; j < NB; j++)
                s += __shfl_sync(0x000000ffu, e, j);
            g_bw[b * NB + i] = e / s;
        }
        __syncwarp(0xffffffffu);
        if (threadIdx.x == 0)
            red_release_add(&g_ready, 1);   // orders the 8 g_bw stores
    }

    // ---------------- band indices (independent of weights) ----------------
    const int base = (blockIdx.x * TPB + threadIdx.x) * 4;   // always < HWR
    const float max_r = sqrtf(0.5f);                          // bit-exact

    int band[4];
    #pragma unroll
    for (int j = 0; j < 4; j++) {
        int p  = base + j;
        int h  = p / WR;
        int wc = p - h * WR;
        float u = (float)wc * (1.0f / 1024.0f);
        float v = (float)(h < H_SZ / 2 ? h : h - H_SZ) * (1.0f / 1024.0f);
        float r = sqrtf(u * u + v * v);                       // exact args

        int bi = 0;
        #pragma unroll
        for (int i = 1; i < NB; i++)
            bi += (r >= max_r * ((float)i / (float)NB)) ? 1 : 0;
        band[j] = (r >= max_r) ? 8 : bi;                      // 8 -> zero slot
    }

    // ---------------- acquire-spin until all 64 rows published -------------
    if (threadIdx.x == 0) {
        while (ld_acquire_gpu(&g_ready) != B_SZ)
            __nanosleep(64);
    }
    __syncthreads();   // broadcasts the acquire to the whole block

    __shared__ float bw[B_SZ * 9];
    for (int i = threadIdx.x; i < B_SZ * 9; i += TPB) {
        int b = i / 9, s = i - b * 9;
        bw[i] = (s < NB) ? g_bw[b * NB + s] : 0.0f;
    }
    __syncthreads();

    // ---------------- streaming stores: 64 planes x float4 -----------------
    float* o = out + base;
    #pragma unroll 4
    for (int b = 0; b < B_SZ; b++) {
        const float* row = bw + b * 9;
        float4 v4;
        v4.x = row[band[0]];
        v4.y = row[band[1]];
        v4.z = row[band[2]];
        v4.w = row[band[3]];
        __stcs(reinterpret_cast<float4*>(o + (size_t)b * HWR), v4);
    }

    // ---------------- reset handshake for next graph replay ----------------
    __syncthreads();
    if (threadIdx.x == 0) {
        int d = atomicAdd(&g_done, 1);
        if (d == GRID - 1) {
            g_ready = 0;
            g_done  = 0;
        }
    }
}

// ---------------------------------------------------------------------------
extern "C" void kernel_launch(void* const* d_in, const int* in_sizes, int n_in,
                              void* d_out, int out_size) {
    const float* feat = (const float*)d_in[0];  // [64, 512]
    const float* w    = (const float*)d_in[1];  // [8, 512]
    const float* bias = (const float*)d_in[2];  // [8]
    float* out = (float*)d_out;                 // [64, 1, 1024, 513] fp32

    fused_freqmask_kernel<<<GRID, TPB>>>(feat, w, bias, out);
}